// round 1
// baseline (speedup 1.0000x reference)
#include <cuda_runtime.h>

// VectorQuantizer: z [16,4096,64] f32, W [4096,64] f32
// out = [loss, z_q (16*4096*64)] f32   (loss omitted if out_size == N*DIM)
//
// Distances replicated exactly as the reference expansion:
//   D_k = fl( fl(z2 + w2_k) - fl(2 * dot_k) )
// argmin with strict '<' scanning k ascending (first index wins ties).
// z_q_out replicates the straight-through estimator rounding:
//   out_j = fl( z_j + fl(w_j - z_j) )

#define NROWS 65536
#define KC    4096
#define DIM   64
#define TK    128          // codes per shared tile (32 KB)
#define CTA   256
#define NBLK  (NROWS / CTA) // 256

__device__ float g_w2[KC];
__device__ float g_part[NBLK];

// packed fp32x2 FMA: acc.lo += a.lo*b.lo ; acc.hi += a.hi*b.hi  (Blackwell-only)
__device__ __forceinline__ void fma2(unsigned long long& acc,
                                     unsigned long long a,
                                     unsigned long long b) {
    asm("fma.rn.f32x2 %0, %1, %2, %0;" : "+l"(acc) : "l"(a), "l"(b));
}

__device__ __forceinline__ float2 unpk(unsigned long long v) {
    float2 r;
    asm("mov.b64 {%0, %1}, %2;" : "=f"(r.x), "=f"(r.y) : "l"(v));
    return r;
}

// ---------------------------------------------------------------------------
// w2[k] = sum_j W[k][j]^2
// ---------------------------------------------------------------------------
__global__ void w2_kernel(const float* __restrict__ W) {
    int k = blockIdx.x * blockDim.x + threadIdx.x;
    if (k < KC) {
        const float* w = W + (size_t)k * DIM;
        float s = 0.0f;
        #pragma unroll
        for (int j = 0; j < DIM; j++) s = __fmaf_rn(w[j], w[j], s);
        g_w2[k] = s;
    }
}

// ---------------------------------------------------------------------------
// Fused distance + argmin + gather + STE output + loss partial
// ---------------------------------------------------------------------------
__global__ __launch_bounds__(CTA)
void vq_kernel(const float* __restrict__ z,
               const float* __restrict__ W,
               float* __restrict__ out,
               int zq_off) {
    __shared__ ulonglong2 ws[TK * 16];   // TK codes x 64 f32 = 32 KB
    __shared__ float w2s[TK];
    __shared__ float red[CTA];

    const int r = blockIdx.x * CTA + threadIdx.x;

    // Load this thread's z row into registers as 16 x (4 floats packed as 2 f32x2)
    const ulonglong2* zp = (const ulonglong2*)(z + (size_t)r * DIM);
    ulonglong2 zv[16];
    #pragma unroll
    for (int i = 0; i < 16; i++) zv[i] = zp[i];

    // z2 = sum z^2 (fp32, fixed order)
    float z2 = 0.0f;
    #pragma unroll
    for (int i = 0; i < 16; i++) {
        float2 a = unpk(zv[i].x), b = unpk(zv[i].y);
        z2 = __fmaf_rn(a.x, a.x, z2);
        z2 = __fmaf_rn(a.y, a.y, z2);
        z2 = __fmaf_rn(b.x, b.x, z2);
        z2 = __fmaf_rn(b.y, b.y, z2);
    }

    float best = __int_as_float(0x7f800000);  // +inf
    int bestk = 0;

    for (int t0 = 0; t0 < KC; t0 += TK) {
        __syncthreads();
        // cooperative tile load: TK*64 floats = TK*16 ulonglong2, coalesced
        const ulonglong2* wp = (const ulonglong2*)(W + (size_t)t0 * DIM);
        #pragma unroll 4
        for (int i = threadIdx.x; i < TK * 16; i += CTA) ws[i] = wp[i];
        if (threadIdx.x < TK) w2s[threadIdx.x] = g_w2[t0 + threadIdx.x];
        __syncthreads();

        #pragma unroll 2
        for (int c = 0; c < TK; c++) {
            unsigned long long acc0 = 0ull, acc1 = 0ull;  // (0.0f,0.0f) bit patterns
            const ulonglong2* wv = ws + c * 16;
            #pragma unroll
            for (int i = 0; i < 16; i++) {
                ulonglong2 w = wv[i];          // broadcast LDS.128
                fma2(acc0, zv[i].x, w.x);
                fma2(acc1, zv[i].y, w.y);
            }
            float2 s0 = unpk(acc0), s1 = unpk(acc1);
            float dot = __fadd_rn(__fadd_rn(s0.x, s1.x), __fadd_rn(s0.y, s1.y));
            // D = fl( fl(z2 + w2) - fl(2*dot) )  -- separate roundings, no FMA contraction
            float A = __fadd_rn(z2, w2s[c]);
            float D = __fsub_rn(A, __fmul_rn(2.0f, dot));
            int k = t0 + c;
            if (D < best) { best = D; bestk = k; }   // strict <: first index wins ties
        }
    }

    // Epilogue: gather W[bestk], STE output, loss partial
    const float* wq = W + (size_t)bestk * DIM;
    float* o = out + zq_off + (size_t)r * DIM;
    float lsum = 0.0f;
    #pragma unroll
    for (int i = 0; i < 16; i++) {
        float2 a = unpk(zv[i].x), b = unpk(zv[i].y);
        float zz[4] = {a.x, a.y, b.x, b.y};
        #pragma unroll
        for (int q = 0; q < 4; q++) {
            float w = wq[4 * i + q];
            float d = __fsub_rn(zz[q], w);            // z - z_q (loss term)
            lsum = __fmaf_rn(d, d, lsum);
            o[4 * i + q] = __fadd_rn(zz[q], __fsub_rn(w, zz[q]));  // STE rounding
        }
    }

    // Deterministic CTA reduction of loss partials
    red[threadIdx.x] = lsum;
    __syncthreads();
    for (int s = CTA / 2; s > 0; s >>= 1) {
        if (threadIdx.x < s)
            red[threadIdx.x] = __fadd_rn(red[threadIdx.x], red[threadIdx.x + s]);
        __syncthreads();
    }
    if (threadIdx.x == 0) g_part[blockIdx.x] = red[0];
}

// ---------------------------------------------------------------------------
// Final loss: 0.25 * mean  (divides by powers of two -> exact scaling)
// ---------------------------------------------------------------------------
__global__ void loss_kernel(float* __restrict__ out) {
    float s = 0.0f;
    #pragma unroll 8
    for (int i = 0; i < NBLK; i++) s = __fadd_rn(s, g_part[i]);
    out[0] = __fmul_rn(0.25f, __fdiv_rn(s, 4194304.0f));
}

extern "C" void kernel_launch(void* const* d_in, const int* in_sizes, int n_in,
                              void* d_out, int out_size) {
    const float* z = (const float*)d_in[0];
    const float* W = (const float*)d_in[1];
    // defensive: z is the larger tensor
    if (n_in >= 2 && in_sizes[0] < in_sizes[1]) {
        const float* t = z; z = W; W = t;
    }
    float* out = (float*)d_out;
    const int zq_off = (out_size > NROWS * DIM) ? 1 : 0;

    w2_kernel<<<KC / 256, 256>>>(W);
    vq_kernel<<<NBLK, CTA>>>(z, W, out, zq_off);
    if (zq_off) loss_kernel<<<1, 1>>>(out);
}

// round 2
// speedup vs baseline: 1.3387x; 1.3387x over previous
#include <cuda_runtime.h>

// VectorQuantizer: z [16,4096,64] f32, W [4096,64] f32
// out = [loss, z_q (16*4096*64)] f32
//
// Register-tiled FFMA2 distance kernel:
//   CTA tile: 128 rows x 64 codes. Thread tile: 8 rows (4 f32x2 pairs) x 4 codes.
//   Distances bit-replicate the reference expansion:
//     D_k = fl( fl(z2 + w2_k) - fl(2 * dot_k) ),  dot accumulated k-ascending fp32.
//   argmin via u64 key (D_bits<<32 | k): min == (smallest D, first index on tie).
//   STE output: out_j = fl( z_j + fl(w_j - z_j) ).

#define NROWS 65536
#define KC    4096
#define DIM   64
#define ROWS_B 128
#define CODES_B 64
#define NTILES (KC / CODES_B)     // 64
#define CTA   256
#define NBLK  (NROWS / ROWS_B)    // 512
#define ZPITCH 66                 // u64 per k-row (padded: kills STS bank conflicts)
#define WPITCH 68                 // floats per k-row (padded, keeps 16B alignment)

// shared layout (bytes)
#define ZSH_OFF   0
#define WSH_OFF   33792           // 64*66*8
#define REDK_OFF  51200           // + 64*68*4
#define Z2_OFF    67584           // + 128*16*8
#define W2_OFF    68096
#define BIDX_OFF  68352
#define SMEM_BYTES 68864

typedef unsigned long long u64;

__device__ float g_w2[KC];
__device__ float g_part[NBLK];

// packed fp32x2 FMA (Blackwell FFMA2): acc.lo += a.lo*b.lo ; acc.hi += a.hi*b.hi
__device__ __forceinline__ void fma2(u64& acc, u64 a, u64 b) {
    asm("fma.rn.f32x2 %0, %1, %2, %0;" : "+l"(acc) : "l"(a), "l"(b));
}
__device__ __forceinline__ u64 dup2(float w) {
    u64 r; asm("mov.b64 %0, {%1, %1};" : "=l"(r) : "f"(w)); return r;
}
__device__ __forceinline__ float2 unpk(u64 v) {
    float2 r; asm("mov.b64 {%0, %1}, %2;" : "=f"(r.x), "=f"(r.y) : "l"(v)); return r;
}

// ---------------------------------------------------------------------------
__global__ void w2_kernel(const float* __restrict__ W) {
    int k = blockIdx.x * blockDim.x + threadIdx.x;
    if (k < KC) {
        const float* w = W + (size_t)k * DIM;
        float s = 0.0f;
        #pragma unroll
        for (int j = 0; j < DIM; j++) s = __fmaf_rn(w[j], w[j], s);
        g_w2[k] = s;
    }
}

// ---------------------------------------------------------------------------
__global__ __launch_bounds__(CTA, 2)
void vq_kernel(const float* __restrict__ z,
               const float* __restrict__ W,
               float* __restrict__ out,
               int zq_off) {
    extern __shared__ char sm[];
    u64*   zsh  = (u64*)(sm + ZSH_OFF);    // [k][row_pair] pitch ZPITCH
    float* wsh  = (float*)(sm + WSH_OFF);  // [k][code]     pitch WPITCH
    u64*   redk = (u64*)(sm + REDK_OFF);   // [row][tx] argmin candidates
    float* z2sh = (float*)(sm + Z2_OFF);
    float* w2sh = (float*)(sm + W2_OFF);
    int*   bidx = (int*)(sm + BIDX_OFF);
    float* zshf = (float*)zsh;

    const int tid = threadIdx.x;
    const int ty = tid >> 4, tx = tid & 15;
    const int rp0 = ty * 4;                // row pairs rp0..rp0+3 -> rows ty*8..ty*8+7
    const int c0  = tx * 4;                // codes c0..c0+3 within tile

    // ---- load z tile (transposed, row-pair packed), coalesced float4 reads ----
    const float4* gz = (const float4*)(z + (size_t)blockIdx.x * ROWS_B * DIM);
    #pragma unroll
    for (int q = 0; q < 8; q++) {
        int i = tid + CTA * q;             // 2048 float4 chunks
        int r = i >> 4, kc = (i & 15) << 2;
        float4 v = gz[i];
        float vv[4] = {v.x, v.y, v.z, v.w};
        #pragma unroll
        for (int j = 0; j < 4; j++)
            zshf[((kc + j) * ZPITCH + (r >> 1)) * 2 + (r & 1)] = vv[j];
    }
    __syncthreads();

    // ---- z2 per row: sequential k-ascending (matches R1 proven order) ----
    if (tid < ROWS_B) {
        float s = 0.0f;
        for (int k = 0; k < DIM; k++) {
            float v = zshf[(k * ZPITCH + (tid >> 1)) * 2 + (tid & 1)];
            s = __fmaf_rn(v, v, s);
        }
        z2sh[tid] = s;
    }
    __syncthreads();

    float z2r[8];
    #pragma unroll
    for (int j = 0; j < 8; j++) z2r[j] = z2sh[ty * 8 + j];

    u64 best[8];
    #pragma unroll
    for (int j = 0; j < 8; j++) best[j] = 0x7f80000000000000ULL;  // (+inf, k=0)

    u64 acc[4][4];   // acc[ci][rj] : (dot row 2(rp0+rj), dot row 2(rp0+rj)+1)

    for (int t = 0; t < NTILES; t++) {
        const int t0 = t * CODES_B;
        __syncthreads();   // previous tile's wsh readers done

        // W tile load (transposed into [k][c]), coalesced
        const float4* gw = (const float4*)(W + (size_t)t0 * DIM);
        #pragma unroll
        for (int q = 0; q < 4; q++) {
            int i = tid + CTA * q;         // 1024 float4 chunks
            int c = i >> 4, kc = (i & 15) << 2;
            float4 v = gw[i];
            float vv[4] = {v.x, v.y, v.z, v.w};
            #pragma unroll
            for (int j = 0; j < 4; j++) wsh[(kc + j) * WPITCH + c] = vv[j];
        }
        if (tid < CODES_B) w2sh[tid] = g_w2[t0 + tid];
        __syncthreads();

        #pragma unroll
        for (int ci = 0; ci < 4; ci++)
            #pragma unroll
            for (int rj = 0; rj < 4; rj++) acc[ci][rj] = 0ULL;

        // ---- main FFMA2 loop: 16 FMA2 per k-step per thread ----
        #pragma unroll 16
        for (int k = 0; k < DIM; k++) {
            ulonglong2 za = *(const ulonglong2*)(zsh + k * ZPITCH + rp0);
            ulonglong2 zb = *(const ulonglong2*)(zsh + k * ZPITCH + rp0 + 2);
            float4 wv = *(const float4*)(wsh + k * WPITCH + c0);
            u64 w0 = dup2(wv.x), w1 = dup2(wv.y), w2 = dup2(wv.z), w3 = dup2(wv.w);
            fma2(acc[0][0], za.x, w0); fma2(acc[0][1], za.y, w0);
            fma2(acc[0][2], zb.x, w0); fma2(acc[0][3], zb.y, w0);
            fma2(acc[1][0], za.x, w1); fma2(acc[1][1], za.y, w1);
            fma2(acc[1][2], zb.x, w1); fma2(acc[1][3], zb.y, w1);
            fma2(acc[2][0], za.x, w2); fma2(acc[2][1], za.y, w2);
            fma2(acc[2][2], zb.x, w2); fma2(acc[2][3], zb.y, w2);
            fma2(acc[3][0], za.x, w3); fma2(acc[3][1], za.y, w3);
            fma2(acc[3][2], zb.x, w3); fma2(acc[3][3], zb.y, w3);
        }

        // ---- per-tile distance + argmin update ----
        #pragma unroll
        for (int ci = 0; ci < 4; ci++) {
            float w2c = w2sh[c0 + ci];
            u64 kk = (u64)(t0 + c0 + ci);
            #pragma unroll
            for (int rj = 0; rj < 4; rj++) {
                float2 dd = unpk(acc[ci][rj]);
                float A0 = __fadd_rn(z2r[2 * rj],     w2c);
                float A1 = __fadd_rn(z2r[2 * rj + 1], w2c);
                float D0 = __fsub_rn(A0, __fmul_rn(2.0f, dd.x));
                float D1 = __fsub_rn(A1, __fmul_rn(2.0f, dd.y));
                u64 k0 = ((u64)__float_as_uint(D0) << 32) | kk;
                u64 k1 = ((u64)__float_as_uint(D1) << 32) | kk;
                if (k0 < best[2 * rj])     best[2 * rj]     = k0;
                if (k1 < best[2 * rj + 1]) best[2 * rj + 1] = k1;
            }
        }
    }

    // ---- cross-thread argmin reduction (16 tx candidates per row) ----
    #pragma unroll
    for (int j = 0; j < 8; j++) redk[(ty * 8 + j) * 16 + tx] = best[j];
    __syncthreads();
    if (tid < ROWS_B) {
        u64 b = redk[tid * 16];
        #pragma unroll
        for (int i = 1; i < 16; i++) {
            u64 v = redk[tid * 16 + i];
            if (v < b) b = v;
        }
        bidx[tid] = (int)(b & 0xffffffffULL);
    }
    __syncthreads();

    // ---- gather + STE output + loss partial ----
    float lsum = 0.0f;
    float* ob = out + zq_off + (size_t)blockIdx.x * ROWS_B * DIM;
    #pragma unroll 4
    for (int q = 0; q < 32; q++) {
        int idx = tid + CTA * q;
        int row = idx >> 6, k = idx & 63;
        float zz = zshf[(k * ZPITCH + (row >> 1)) * 2 + (row & 1)];
        float w  = W[(size_t)bidx[row] * DIM + k];
        float d  = __fsub_rn(zz, w);
        lsum = __fmaf_rn(d, d, lsum);
        ob[idx] = __fadd_rn(zz, __fsub_rn(w, zz));   // STE rounding
    }

    // deterministic CTA loss reduction (reuse redk space)
    float* redf = (float*)redk;
    redf[tid] = lsum;
    __syncthreads();
    for (int s = CTA / 2; s > 0; s >>= 1) {
        if (tid < s) redf[tid] = __fadd_rn(redf[tid], redf[tid + s]);
        __syncthreads();
    }
    if (tid == 0) g_part[blockIdx.x] = redf[0];
}

// ---------------------------------------------------------------------------
__global__ void loss_kernel(float* __restrict__ out) {
    float s = 0.0f;
    #pragma unroll 8
    for (int i = 0; i < NBLK; i++) s = __fadd_rn(s, g_part[i]);
    out[0] = __fmul_rn(0.25f, __fdiv_rn(s, 4194304.0f));
}

extern "C" void kernel_launch(void* const* d_in, const int* in_sizes, int n_in,
                              void* d_out, int out_size) {
    const float* z = (const float*)d_in[0];
    const float* W = (const float*)d_in[1];
    if (n_in >= 2 && in_sizes[0] < in_sizes[1]) {
        const float* t = z; z = W; W = t;
    }
    float* out = (float*)d_out;
    const int zq_off = (out_size > NROWS * DIM) ? 1 : 0;

    cudaFuncSetAttribute(vq_kernel, cudaFuncAttributeMaxDynamicSharedMemorySize,
                         SMEM_BYTES);
    w2_kernel<<<KC / 256, 256>>>(W);
    vq_kernel<<<NBLK, CTA, SMEM_BYTES>>>(z, W, out, zq_off);
    if (zq_off) loss_kernel<<<1, 1>>>(out);
}

// round 4
// speedup vs baseline: 2.0201x; 1.5090x over previous
#include <cuda_runtime.h>
#include <cuda_bf16.h>

typedef unsigned long long u64;
typedef unsigned int u32;

#define NROWS  65536
#define KC     4096
#define DIM    64
#define ROWS_B 128
#define NTILES 64          // B tiles of 64 codes
#define NBLK   512
#define CTA    256
#define MARGIN 1e-5f
#define ZP     68          // zsm pitch (floats)

// dynamic smem layout (bytes)
#define OFF_Z   0                         // 128*68*4 = 34816
#define OFF_Z2  34816                     // 128 floats
#define OFF_AHI 35328                     // 16384 (128B aligned)
#define OFF_ALO 51712                     // 16384
#define OFF_B(buf,m) (68096 + (buf)*16384 + (m)*8192)   // m: 0=hi 1=lo
#define OFF_W2(buf)  (100864 + (buf)*256)
#define SMEM_BYTES 101376

#define SWZ(x) ((x) ^ (((x) >> 3) & 0x70))

__device__ __nv_bfloat16 g_whi[KC * DIM];
__device__ __nv_bfloat16 g_wlo[KC * DIM];
__device__ float g_w2[KC];
__device__ int   g_idx[NROWS];
__device__ float g_part[4096];

// ---------------------------------------------------------------------------
__device__ __forceinline__ u32 smem_u32(const void* p) {
    u32 a;
    asm("{ .reg .u64 t; cvta.to.shared.u64 t, %1; cvt.u32.u64 %0, t; }"
        : "=r"(a) : "l"(p));
    return a;
}
__device__ __forceinline__ void cp16(u32 dst, const void* src) {
    asm volatile("cp.async.cg.shared.global [%0], [%1], 16;"
                 :: "r"(dst), "l"(src));
}
#define CP_COMMIT() asm volatile("cp.async.commit_group;" ::: "memory")
#define CP_WAIT0()  asm volatile("cp.async.wait_group 0;" ::: "memory")

__device__ __forceinline__ void ldsm4(u32& r0, u32& r1, u32& r2, u32& r3, u32 a) {
    asm volatile("ldmatrix.sync.aligned.m8n8.x4.shared.b16 {%0,%1,%2,%3}, [%4];"
                 : "=r"(r0), "=r"(r1), "=r"(r2), "=r"(r3) : "r"(a));
}
#define MMA(d, a, b0, b1)                                                     \
    asm volatile("mma.sync.aligned.m16n8k16.row.col.f32.bf16.bf16.f32 "       \
        "{%0,%1,%2,%3},{%4,%5,%6,%7},{%8,%9},{%0,%1,%2,%3};"                  \
        : "+f"((d)[0]), "+f"((d)[1]), "+f"((d)[2]), "+f"((d)[3])              \
        : "r"((a)[0]), "r"((a)[1]), "r"((a)[2]), "r"((a)[3]), "r"(b0), "r"(b1))

// ---------------------------------------------------------------------------
// prep: exact w2 (sequential, matches R1/R2) + bf16 hi/lo split of -2W
// ---------------------------------------------------------------------------
__global__ void prep_kernel(const float* __restrict__ W) {
    int k = blockIdx.x * 32 + threadIdx.x;   // grid 128 x 32
    float s = 0.0f;
    #pragma unroll 8
    for (int j = 0; j < DIM; j++) {
        float wv = W[k * DIM + j];
        s = __fmaf_rn(wv, wv, s);
        float wp = -2.0f * wv;               // exact scale
        __nv_bfloat16 h = __float2bfloat16(wp);
        float r = __fsub_rn(wp, __bfloat162float(h));
        g_whi[k * DIM + j] = h;
        g_wlo[k * DIM + j] = __float2bfloat16(r);
    }
    g_w2[k] = s;
}

// ---------------------------------------------------------------------------
__device__ __forceinline__ u64 rescore(int k, const float* zr, float z2r,
                                       const float* __restrict__ W) {
    const float* wr = W + (size_t)k * DIM;
    float s = 0.0f;
    #pragma unroll 8
    for (int j = 0; j < DIM; j++) s = __fmaf_rn(zr[j], wr[j], s);
    float D = __fsub_rn(__fadd_rn(z2r, g_w2[k]), __fmul_rn(2.0f, s));
    return ((u64)__float_as_uint(D) << 32) | (u32)k;
}

__device__ __forceinline__ void load_tile(u32 sb, int t, int buf, int tid) {
    const char* bh = (const char*)g_whi;
    const char* bl = (const char*)g_wlo;
    size_t gbase = (size_t)t * 64 * 128;     // 64 codes * 128B
    #pragma unroll
    for (int q = 0; q < 2; q++) {
        int i = tid + CTA * q;               // 512 chunks of 16B
        u32 sw = SWZ((u32)(i * 16));
        cp16(sb + OFF_B(buf, 0) + sw, bh + gbase + (size_t)i * 16);
        cp16(sb + OFF_B(buf, 1) + sw, bl + gbase + (size_t)i * 16);
    }
    if (tid < 16)
        cp16(sb + OFF_W2(buf) + tid * 16,
             (const char*)g_w2 + (size_t)t * 256 + tid * 16);
}

// ---------------------------------------------------------------------------
// main: split-bf16 HMMA distances + top-3 tracking + exact rescore
// ---------------------------------------------------------------------------
__global__ __launch_bounds__(CTA, 2)
void vq_main(const float* __restrict__ z, const float* __restrict__ W) {
    extern __shared__ char sm[];
    const u32 sb = smem_u32(sm);
    const int tid = threadIdx.x, wid = tid >> 5, lane = tid & 31;
    float* zsm = (float*)(sm + OFF_Z);
    float* z2s = (float*)(sm + OFF_Z2);

    // ---- z -> smem (coalesced) ----
    const float4* gz = (const float4*)(z + (size_t)blockIdx.x * ROWS_B * DIM);
    #pragma unroll
    for (int q = 0; q < 8; q++) {
        int i = tid + CTA * q;               // 2048 float4
        int r = i >> 4, c = i & 15;
        *(float4*)(zsm + r * ZP + c * 4) = gz[i];
    }
    load_tile(sb, 0, 0, tid);
    CP_COMMIT();
    __syncthreads();

    // ---- build A_hi/A_lo (swizzled bf16x2) + z2 ----
    #pragma unroll
    for (int q = 0; q < 16; q++) {
        int i = tid + CTA * q;               // 4096 u32 slots
        int r = i >> 5, pr = i & 31;
        float a = zsm[r * ZP + 2 * pr], b = zsm[r * ZP + 2 * pr + 1];
        __nv_bfloat16 ha = __float2bfloat16(a), hb = __float2bfloat16(b);
        __nv_bfloat162 h2 = __halves2bfloat162(ha, hb);
        float ra = __fsub_rn(a, __bfloat162float(ha));
        float rb = __fsub_rn(b, __bfloat162float(hb));
        __nv_bfloat162 l2 = __halves2bfloat162(__float2bfloat16(ra),
                                               __float2bfloat16(rb));
        u32 sw = SWZ((u32)(r * 128 + pr * 4));
        *(u32*)(sm + OFF_AHI + sw) = *(u32*)&h2;
        *(u32*)(sm + OFF_ALO + sw) = *(u32*)&l2;
    }
    if (tid < ROWS_B) {
        float s = 0.0f;
        #pragma unroll 8
        for (int j = 0; j < DIM; j++) {
            float v = zsm[tid * ZP + j];
            s = __fmaf_rn(v, v, s);
        }
        z2s[tid] = s;
    }
    __syncthreads();

    // ---- A fragments (held in registers for all tiles) ----
    u32 ahi[4][4], alo[4][4];
    {
        int mat = lane >> 3, rl = lane & 7;
        u32 abase = (u32)((wid * 16 + (mat & 1) * 8 + rl) * 128 + (mat >> 1) * 16);
        #pragma unroll
        for (int kc = 0; kc < 4; kc++) {
            u32 sw = SWZ(abase + kc * 32);
            ldsm4(ahi[kc][0], ahi[kc][1], ahi[kc][2], ahi[kc][3], sb + OFF_AHI + sw);
            ldsm4(alo[kc][0], alo[kc][1], alo[kc][2], alo[kc][3], sb + OFF_ALO + sw);
        }
    }

    const int tg = lane & 3, rq = lane >> 2;
    float s1[2], s2[2], s3[2];
    int k1[2], k2[2];
    #pragma unroll
    for (int p = 0; p < 2; p++) {
        s1[p] = s2[p] = s3[p] = __int_as_float(0x7f800000);
        k1[p] = k2[p] = 0;
    }

    const int brl = lane & 7;
    const u32 bkoff = (u32)(((lane >> 4) * 32) + (((lane >> 3) & 1) * 16));

    for (int t = 0; t < NTILES; t++) {
        int buf = t & 1;
        CP_WAIT0();
        __syncthreads();
        if (t + 1 < NTILES) { load_tile(sb, t + 1, (t + 1) & 1, tid); CP_COMMIT(); }

        const u32 bhB = sb + OFF_B(buf, 0);
        const u32 blB = sb + OFF_B(buf, 1);
        const float* w2b = (const float*)(sm + OFF_W2(buf));

        float d[8][4];
        #pragma unroll
        for (int n = 0; n < 8; n++)
            #pragma unroll
            for (int c = 0; c < 4; c++) d[n][c] = 0.0f;

        #pragma unroll
        for (int g = 0; g < 2; g++) {
            #pragma unroll
            for (int kp = 0; kp < 2; kp++) {
                u32 bh[4][4], bl[4][4];
                #pragma unroll
                for (int i = 0; i < 4; i++) {
                    u32 off = SWZ((u32)(((g * 4 + i) * 8 + brl) * 128)
                                  + (u32)(2 * kp * 32) + bkoff);
                    ldsm4(bh[i][0], bh[i][1], bh[i][2], bh[i][3], bhB + off);
                    ldsm4(bl[i][0], bl[i][1], bl[i][2], bl[i][3], blB + off);
                }
                // round-robin over 4 independent accumulators (hides HMMA latency)
                #pragma unroll
                for (int i = 0; i < 4; i++) MMA(d[g*4+i], ahi[2*kp],   bh[i][0], bh[i][1]);
                #pragma unroll
                for (int i = 0; i < 4; i++) MMA(d[g*4+i], ahi[2*kp+1], bh[i][2], bh[i][3]);
                #pragma unroll
                for (int i = 0; i < 4; i++) MMA(d[g*4+i], alo[2*kp],   bh[i][0], bh[i][1]);
                #pragma unroll
                for (int i = 0; i < 4; i++) MMA(d[g*4+i], alo[2*kp+1], bh[i][2], bh[i][3]);
                #pragma unroll
                for (int i = 0; i < 4; i++) MMA(d[g*4+i], ahi[2*kp],   bl[i][0], bl[i][1]);
                #pragma unroll
                for (int i = 0; i < 4; i++) MMA(d[g*4+i], ahi[2*kp+1], bl[i][2], bl[i][3]);
            }
        }

        // ---- extract + top-3 tracking ----
        #pragma unroll
        for (int nc = 0; nc < 8; nc++) {
            float2 wv = *(const float2*)(w2b + nc * 8 + 2 * tg);
            int kb = t * 64 + nc * 8 + 2 * tg;
            float Dv[4] = { __fadd_rn(wv.x, d[nc][0]), __fadd_rn(wv.y, d[nc][1]),
                            __fadd_rn(wv.x, d[nc][2]), __fadd_rn(wv.y, d[nc][3]) };
            int   kv[4] = { kb, kb + 1, kb, kb + 1 };
            #pragma unroll
            for (int q = 0; q < 4; q++) {
                int p = q >> 1;
                float D = Dv[q];
                if (D < s3[p]) {
                    if (D < s1[p]) { s3[p]=s2[p]; s2[p]=s1[p]; k2[p]=k1[p];
                                     s1[p]=D; k1[p]=kv[q]; }
                    else if (D < s2[p]) { s3[p]=s2[p]; s2[p]=D; k2[p]=kv[q]; }
                    else s3[p] = D;
                }
            }
        }
    }

    // ---- per-row combine + exact rescore ----
    int flag[2];
    #pragma unroll
    for (int p = 0; p < 2; p++) {
        int rowc = wid * 16 + p * 8 + rq;
        float g = s1[p];
        g = fminf(g, __shfl_xor_sync(0xffffffffu, g, 1));
        g = fminf(g, __shfl_xor_sync(0xffffffffu, g, 2));
        float thr = __fadd_rn(g, MARGIN);
        flag[p] = (s3[p] <= thr) ? 1 : 0;

        u64 key = ~0ull;
        if (s1[p] <= thr) { u64 v = rescore(k1[p], zsm + rowc * ZP, z2s[rowc], W);
                            if (v < key) key = v; }
        if (s2[p] <= thr) { u64 v = rescore(k2[p], zsm + rowc * ZP, z2s[rowc], W);
                            if (v < key) key = v; }
        u64 o = __shfl_xor_sync(0xffffffffu, key, 1); if (o < key) key = o;
        o = __shfl_xor_sync(0xffffffffu, key, 2); if (o < key) key = o;
        if (tg == 0)
            g_idx[blockIdx.x * ROWS_B + rowc] = (int)(key & 0xffffffffULL);
    }

    // ---- cooperative exact full-rescan for flagged rows (rare) ----
    __syncwarp();
    #pragma unroll
    for (int p = 0; p < 2; p++) {
        unsigned f = __ballot_sync(0xffffffffu, flag[p] != 0);
        for (int r = 0; r < 8; r++) {
            if ((f >> (4 * r)) & 0xF) {
                int rowc = wid * 16 + p * 8 + r;
                const float* zr = zsm + rowc * ZP;
                float z2r = z2s[rowc];
                u64 bk = ~0ull;
                for (int k = lane; k < KC; k += 32) {
                    u64 v = rescore(k, zr, z2r, W);
                    if (v < bk) bk = v;
                }
                #pragma unroll
                for (int o = 16; o; o >>= 1) {
                    u64 v = __shfl_xor_sync(0xffffffffu, bk, o);
                    if (v < bk) bk = v;
                }
                if (lane == 0)
                    g_idx[blockIdx.x * ROWS_B + rowc] = (int)(bk & 0xffffffffULL);
            }
        }
    }
}

// ---------------------------------------------------------------------------
// output: gather + STE + loss partials
// ---------------------------------------------------------------------------
__global__ __launch_bounds__(256)
void vq_out(const float* __restrict__ z, const float* __restrict__ W,
            float* __restrict__ out, int off) {
    __shared__ float red[256];
    int e0 = (blockIdx.x * 256 + threadIdx.x) * 4;
    int idx = g_idx[e0 >> 6];
    float4 zv = *(const float4*)(z + e0);
    float4 wv = *(const float4*)(W + (size_t)idx * DIM + (e0 & 63));
    float zz[4] = {zv.x, zv.y, zv.z, zv.w};
    float ww[4] = {wv.x, wv.y, wv.z, wv.w};
    float lsum = 0.0f;
    #pragma unroll
    for (int q = 0; q < 4; q++) {
        float dd = __fsub_rn(zz[q], ww[q]);
        lsum = __fmaf_rn(dd, dd, lsum);
        out[off + e0 + q] = __fadd_rn(zz[q], __fsub_rn(ww[q], zz[q]));
    }
    red[threadIdx.x] = lsum;
    __syncthreads();
    for (int s = 128; s > 0; s >>= 1) {
        if (threadIdx.x < s)
            red[threadIdx.x] = __fadd_rn(red[threadIdx.x], red[threadIdx.x + s]);
        __syncthreads();
    }
    if (threadIdx.x == 0) g_part[blockIdx.x] = red[0];
}

__global__ void loss_kernel(float* __restrict__ out) {
    __shared__ float red[256];
    float s = 0.0f;
    for (int i = threadIdx.x; i < 4096; i += 256) s = __fadd_rn(s, g_part[i]);
    red[threadIdx.x] = s;
    __syncthreads();
    for (int st = 128; st > 0; st >>= 1) {
        if (threadIdx.x < st)
            red[threadIdx.x] = __fadd_rn(red[threadIdx.x], red[threadIdx.x + st]);
        __syncthreads();
    }
    if (threadIdx.x == 0)
        out[0] = __fmul_rn(0.25f, __fdiv_rn(red[0], 4194304.0f));
}

// ---------------------------------------------------------------------------
extern "C" void kernel_launch(void* const* d_in, const int* in_sizes, int n_in,
                              void* d_out, int out_size) {
    const float* z = (const float*)d_in[0];
    const float* W = (const float*)d_in[1];
    if (n_in >= 2 && in_sizes[0] < in_sizes[1]) {
        const float* t = z; z = W; W = t;
    }
    float* out = (float*)d_out;
    const int off = (out_size > NROWS * DIM) ? 1 : 0;

    cudaFuncSetAttribute(vq_main, cudaFuncAttributeMaxDynamicSharedMemorySize,
                         SMEM_BYTES);
    prep_kernel<<<128, 32>>>(W);
    vq_main<<<NBLK, CTA, SMEM_BYTES>>>(z, W);
    vq_out<<<4096, 256>>>(z, W, out, off);
    if (off) loss_kernel<<<1, 256>>>(out);
}